// round 2
// baseline (speedup 1.0000x reference)
#include <cuda_runtime.h>
#include <cuda_bf16.h>
#include <cstdint>

// ============================================================================
// y[t, :] = weight[x[t], :] + A[x[t], :] @ B
//   tokens M = 16384, DIM N = 1024, RANK K = 256
// Tensor path: mma.sync.m16n8k8.tf32 (legal at compute_103; tcgen05 is NOT).
// ============================================================================
static constexpr int M_TOTAL = 16384;
static constexpr int DIM     = 1024;
static constexpr int RANK    = 256;

static constexpr int TILE_M  = 128;
static constexpr int TILE_N  = 128;
static constexpr int KC      = 32;              // K chunk
static constexpr int NCHUNK  = RANK / KC;       // 8

// Smem tile pitch: 36 floats (144 B, 16B-aligned, conflict-free fragment LDS)
static constexpr int PITCH   = 36;
static constexpr int TILE_FLOATS = 128 * PITCH;              // 4608 floats / tile
static constexpr int SMEM_FLOATS = 4 * TILE_FLOATS;          // A0,A1,B0,B1
static constexpr int SMEM_BYTES  = SMEM_FLOATS * 4 + 512;    // + tokens[128]

// Scratch: transposed B, [DIM][RANK] K-contiguous (1 MB)
__device__ float g_Bt[DIM * RANK];

// ---------------------------------------------------------------------------
__device__ __forceinline__ uint32_t smem_to_u32(const void* p) {
    uint32_t a;
    asm("{ .reg .u64 t; cvta.to.shared.u64 t, %1; cvt.u32.u64 %0, t; }" : "=r"(a) : "l"(p));
    return a;
}

__device__ __forceinline__ void cp_async16(uint32_t dst, const void* src) {
    asm volatile("cp.async.cg.shared.global [%0], [%1], 16;" :: "r"(dst), "l"(src));
}
__device__ __forceinline__ void cp_commit() {
    asm volatile("cp.async.commit_group;" ::: "memory");
}
template <int N>
__device__ __forceinline__ void cp_wait() {
    asm volatile("cp.async.wait_group %0;" :: "n"(N) : "memory");
}

__device__ __forceinline__ uint32_t f2tf32(float f) {
    uint32_t r;
    asm("cvt.rna.tf32.f32 %0, %1;" : "=r"(r) : "f"(f));
    return r;
}

__device__ __forceinline__ void mma_tf32(float* c, const uint32_t* a, const uint32_t* b) {
    asm volatile(
        "mma.sync.aligned.m16n8k8.row.col.f32.tf32.tf32.f32 "
        "{%0,%1,%2,%3}, {%4,%5,%6,%7}, {%8,%9}, {%0,%1,%2,%3};\n"
        : "+f"(c[0]), "+f"(c[1]), "+f"(c[2]), "+f"(c[3])
        : "r"(a[0]), "r"(a[1]), "r"(a[2]), "r"(a[3]), "r"(b[0]), "r"(b[1]));
}

// ============================================================================
// Kernel 1: transpose B [RANK, DIM] -> g_Bt [DIM, RANK]
// ============================================================================
__global__ void transpose_b_kernel(const float* __restrict__ B) {
    __shared__ float t[32][33];
    int n0 = blockIdx.x * 32;
    int k0 = blockIdx.y * 32;
    int tx = threadIdx.x, ty = threadIdx.y;
    #pragma unroll
    for (int j = 0; j < 32; j += 8)
        t[ty + j][tx] = B[(size_t)(k0 + ty + j) * DIM + n0 + tx];
    __syncthreads();
    #pragma unroll
    for (int j = 0; j < 32; j += 8)
        g_Bt[(size_t)(n0 + ty + j) * RANK + k0 + tx] = t[tx][ty + j];
}

// ============================================================================
// Kernel 2: fused gather-GEMM-epilogue
//   grid: (DIM/TILE_N = 8, M_TOTAL/TILE_M = 128)  [N fastest -> A reuse in L2]
//   block: 256 threads = 8 warps, warp grid 2(M) x 4(N), warp tile 64x32
// ============================================================================
__global__ __launch_bounds__(256, 1)
void lora_embed_kernel(const int* __restrict__ x,
                       const float* __restrict__ weight,
                       const float* __restrict__ A,
                       float* __restrict__ out) {
    extern __shared__ float smem[];
    float* As   = smem;                       // [2][128*36]
    float* Bs   = smem + 2 * TILE_FLOATS;     // [2][128*36]
    int* s_tok  = (int*)(smem + SMEM_FLOATS); // [128]

    const int tid  = threadIdx.x;
    const int wid  = tid >> 5;
    const int lane = tid & 31;
    const int group = lane >> 2;   // 0..7
    const int tig   = lane & 3;    // 0..3
    const int warp_m = wid >> 2;   // 0..1
    const int warp_n = wid & 3;    // 0..3

    const int n0 = blockIdx.x * TILE_N;
    const int m0 = blockIdx.y * TILE_M;

    // tokens
    if (tid < 128) s_tok[tid] = x[m0 + tid];

    // loader mapping: 2 threads per row
    const int lrow = tid >> 1;
    const int half = tid & 1;
    const int ltok = x[m0 + lrow];
    const float* a_src_base = A    + (size_t)ltok        * RANK + half * 16;
    const float* b_src_base = g_Bt + (size_t)(n0 + lrow) * RANK + half * 16;

    const uint32_t sb = smem_to_u32(smem);
    const uint32_t a_dst_base = sb + (lrow * PITCH + half * 16) * 4;
    const uint32_t b_dst_base = a_dst_base + 2 * TILE_FLOATS * 4;

    auto prefetch = [&](int c) {
        const int buf = c & 1;
        const uint32_t ad = a_dst_base + buf * TILE_FLOATS * 4;
        const uint32_t bd = b_dst_base + buf * TILE_FLOATS * 4;
        const float* as = a_src_base + c * KC;
        const float* bs = b_src_base + c * KC;
        #pragma unroll
        for (int i = 0; i < 4; i++) {
            cp_async16(ad + i * 16, as + i * 4);
            cp_async16(bd + i * 16, bs + i * 4);
        }
        cp_commit();
    };

    float acc[4][4][4];
    #pragma unroll
    for (int mt = 0; mt < 4; mt++)
        #pragma unroll
        for (int nt = 0; nt < 4; nt++)
            #pragma unroll
            for (int r = 0; r < 4; r++) acc[mt][nt][r] = 0.f;

    prefetch(0);

    for (int c = 0; c < NCHUNK; c++) {
        if (c + 1 < NCHUNK) {
            prefetch(c + 1);
            cp_wait<1>();
        } else {
            cp_wait<0>();
        }
        __syncthreads();

        const float* Ab = As + (c & 1) * TILE_FLOATS;
        const float* Bb = Bs + (c & 1) * TILE_FLOATS;

        #pragma unroll
        for (int ks = 0; ks < 4; ks++) {
            const int k = ks * 8 + tig;
            uint32_t af[4][4];
            #pragma unroll
            for (int mt = 0; mt < 4; mt++) {
                const int r0 = warp_m * 64 + mt * 16 + group;
                af[mt][0] = f2tf32(Ab[r0 * PITCH + k]);
                af[mt][1] = f2tf32(Ab[(r0 + 8) * PITCH + k]);
                af[mt][2] = f2tf32(Ab[r0 * PITCH + k + 4]);
                af[mt][3] = f2tf32(Ab[(r0 + 8) * PITCH + k + 4]);
            }
            uint32_t bf[4][2];
            #pragma unroll
            for (int nt = 0; nt < 4; nt++) {
                const int n = warp_n * 32 + nt * 8 + group;
                bf[nt][0] = f2tf32(Bb[n * PITCH + k]);
                bf[nt][1] = f2tf32(Bb[n * PITCH + k + 4]);
            }
            #pragma unroll
            for (int mt = 0; mt < 4; mt++)
                #pragma unroll
                for (int nt = 0; nt < 4; nt++)
                    mma_tf32(acc[mt][nt], af[mt], bf[nt]);
        }
        __syncthreads();   // protect buffer (c&1) before prefetch(c+2) refills it
    }

    // Epilogue: out = weight[tok] + acc  (fp32, float2 stores)
    #pragma unroll
    for (int mt = 0; mt < 4; mt++) {
        #pragma unroll
        for (int mo = 0; mo < 2; mo++) {
            const int row = warp_m * 64 + mt * 16 + mo * 8 + group;
            const int tok = s_tok[row];
            const float* wrow = weight + (size_t)tok * DIM + n0;
            float* orow = out + (size_t)(m0 + row) * DIM + n0;
            #pragma unroll
            for (int nt = 0; nt < 4; nt++) {
                const int col = warp_n * 32 + nt * 8 + tig * 2;
                float2 w = *(const float2*)(wrow + col);
                float2 o;
                o.x = w.x + acc[mt][nt][mo * 2 + 0];
                o.y = w.y + acc[mt][nt][mo * 2 + 1];
                *(float2*)(orow + col) = o;
            }
        }
    }
}

// ============================================================================
// Launch
// ============================================================================
extern "C" void kernel_launch(void* const* d_in, const int* in_sizes, int n_in,
                              void* d_out, int out_size) {
    const int*   x      = (const int*)d_in[0];       // [16384] int32
    const float* weight = (const float*)d_in[1];     // [128000, 1024]
    const float* A      = (const float*)d_in[2];     // [128000, 256]
    const float* B      = (const float*)d_in[3];     // [256, 1024]
    float* out          = (float*)d_out;             // [16384, 1024]

    (void)in_sizes; (void)n_in; (void)out_size;

    {
        dim3 grid(DIM / 32, RANK / 32);
        dim3 block(32, 8);
        transpose_b_kernel<<<grid, block>>>(B);
    }
    {
        static bool attr_set = false;
        if (!attr_set) {
            cudaFuncSetAttribute(lora_embed_kernel,
                                 cudaFuncAttributeMaxDynamicSharedMemorySize, SMEM_BYTES);
            attr_set = true;
        }
        dim3 grid(DIM / TILE_N, M_TOTAL / TILE_M);   // (8, 128) — N fastest
        lora_embed_kernel<<<grid, 256, SMEM_BYTES>>>(x, weight, A, out);
    }
}

// round 3
// speedup vs baseline: 1.4708x; 1.4708x over previous
#include <cuda_runtime.h>
#include <cuda_fp16.h>
#include <cstdint>

// ============================================================================
// y[t, :] = weight[x[t], :] + A[x[t], :] @ B
//   tokens M = 16384, DIM N = 1024, RANK K = 256
// Tensor path: mma.sync.m16n8k16.f32.f16.f16.f32 (fp16 has same 10-bit
// mantissa as tf32; fp32 accumulate -> same precision, 2x rate, no cvt in loop)
// ============================================================================
static constexpr int M_TOTAL = 16384;
static constexpr int DIM     = 1024;
static constexpr int RANK    = 256;

static constexpr int TILE_M  = 128;
static constexpr int TILE_N  = 128;
static constexpr int KC      = 64;              // K chunk (halves)
static constexpr int NCHUNK  = RANK / KC;       // 4

// Smem: pitch 72 halves (144 B = 9 x 16B) -> conflict-free ldmatrix + LDS
static constexpr int PITCH        = 72;
static constexpr int TILE_HALVES  = 128 * PITCH;          // 9216 halves
static constexpr int TILE_BYTES_S = TILE_HALVES * 2;      // 18432 B
static constexpr int A_REGION     = 2 * TILE_BYTES_S;     // 36864 B (2 bufs)
static constexpr int SMEM_BYTES   = 2 * A_REGION + 512;   // + tokens[128]

// Scratch: half-precision B^T [DIM][RANK] (0.5 MB) and gathered A [M][RANK] (8 MB)
__device__ __half g_Bt[DIM * RANK];
__device__ __half g_Ah[M_TOTAL * RANK];

// ---------------------------------------------------------------------------
__device__ __forceinline__ uint32_t smem_to_u32(const void* p) {
    uint32_t a;
    asm("{ .reg .u64 t; cvta.to.shared.u64 t, %1; cvt.u32.u64 %0, t; }" : "=r"(a) : "l"(p));
    return a;
}
__device__ __forceinline__ void cp_async16(uint32_t dst, const void* src) {
    asm volatile("cp.async.cg.shared.global [%0], [%1], 16;" :: "r"(dst), "l"(src));
}
__device__ __forceinline__ void cp_commit() {
    asm volatile("cp.async.commit_group;" ::: "memory");
}
template <int N>
__device__ __forceinline__ void cp_wait() {
    asm volatile("cp.async.wait_group %0;" :: "n"(N) : "memory");
}
__device__ __forceinline__ void ldmatrix_x4(uint32_t& r0, uint32_t& r1,
                                            uint32_t& r2, uint32_t& r3, uint32_t addr) {
    asm volatile("ldmatrix.sync.aligned.m8n8.x4.shared.b16 {%0,%1,%2,%3}, [%4];"
                 : "=r"(r0), "=r"(r1), "=r"(r2), "=r"(r3) : "r"(addr));
}
__device__ __forceinline__ void mma_f16(float* c, const uint32_t* a, const uint32_t* b) {
    asm volatile(
        "mma.sync.aligned.m16n8k16.row.col.f32.f16.f16.f32 "
        "{%0,%1,%2,%3}, {%4,%5,%6,%7}, {%8,%9}, {%0,%1,%2,%3};\n"
        : "+f"(c[0]), "+f"(c[1]), "+f"(c[2]), "+f"(c[3])
        : "r"(a[0]), "r"(a[1]), "r"(a[2]), "r"(a[3]), "r"(b[0]), "r"(b[1]));
}

// ============================================================================
// Kernel 1: transpose+convert B [RANK, DIM] f32 -> g_Bt [DIM, RANK] half
// ============================================================================
__global__ void transpose_b_kernel(const float* __restrict__ B) {
    __shared__ float t[32][33];
    int n0 = blockIdx.x * 32;
    int k0 = blockIdx.y * 32;
    int tx = threadIdx.x, ty = threadIdx.y;
    #pragma unroll
    for (int j = 0; j < 32; j += 8)
        t[ty + j][tx] = B[(size_t)(k0 + ty + j) * DIM + n0 + tx];
    __syncthreads();
    #pragma unroll
    for (int j = 0; j < 32; j += 8)
        g_Bt[(size_t)(n0 + ty + j) * RANK + k0 + tx] = __float2half_rn(t[tx][ty + j]);
}

// ============================================================================
// Kernel 2: gather+convert A rows: g_Ah[t] = half(A[x[t]]). 8 rows per block.
// ============================================================================
__global__ __launch_bounds__(256)
void gather_a_kernel(const int* __restrict__ x, const float* __restrict__ A) {
    const int row  = blockIdx.x * 8 + (threadIdx.x >> 5);
    const int lane = threadIdx.x & 31;
    const int tok  = x[row];
    const float4* src = (const float4*)(A + (size_t)tok * RANK) + lane * 2;
    float4 v0 = src[0], v1 = src[1];
    __half2 h[4];
    h[0] = __floats2half2_rn(v0.x, v0.y);
    h[1] = __floats2half2_rn(v0.z, v0.w);
    h[2] = __floats2half2_rn(v1.x, v1.y);
    h[3] = __floats2half2_rn(v1.z, v1.w);
    *(uint4*)(g_Ah + (size_t)row * RANK + lane * 8) = *(const uint4*)h;
}

// ============================================================================
// Kernel 3: fused GEMM + weight-gather epilogue
//   grid: (DIM/TILE_N = 8, M_TOTAL/TILE_M = 128)  [N fastest -> Ah reuse in L2]
//   block: 256 threads = 8 warps, warp grid 2(M) x 4(N), warp tile 64x32
// ============================================================================
__global__ __launch_bounds__(256, 1)
void lora_embed_kernel(const int* __restrict__ x,
                       const float* __restrict__ weight,
                       float* __restrict__ out) {
    extern __shared__ __align__(16) char smem[];
    int* s_tok = (int*)(smem + 2 * A_REGION);

    const int tid    = threadIdx.x;
    const int wid    = tid >> 5;
    const int lane   = tid & 31;
    const int group  = lane >> 2;   // 0..7
    const int tig    = lane & 3;    // 0..3
    const int warp_m = wid >> 2;    // 0..1
    const int warp_n = wid & 3;     // 0..3

    const int n0 = blockIdx.x * TILE_N;
    const int m0 = blockIdx.y * TILE_M;

    if (tid < 128) s_tok[tid] = x[m0 + tid];

    const uint32_t sb = smem_to_u32(smem);

    // Loader mapping: 2 threads per row, each covers 32 halves (4x16B) per chunk
    const int lrow  = tid >> 1;
    const int lhalf = tid & 1;
    const __half* a_src = g_Ah + (size_t)(m0 + lrow) * RANK + lhalf * 32;
    const __half* b_src = g_Bt + (size_t)(n0 + lrow) * RANK + lhalf * 32;
    const uint32_t a_dst = sb + (lrow * PITCH + lhalf * 32) * 2;
    const uint32_t b_dst = a_dst + A_REGION;

    auto prefetch = [&](int c) {
        const uint32_t boff = (uint32_t)(c & 1) * TILE_BYTES_S;
        #pragma unroll
        for (int i = 0; i < 4; i++) {
            cp_async16(a_dst + boff + i * 16, a_src + c * KC + i * 8);
            cp_async16(b_dst + boff + i * 16, b_src + c * KC + i * 8);
        }
        cp_commit();
    };

    float acc[4][4][4];
    #pragma unroll
    for (int mt = 0; mt < 4; mt++)
        #pragma unroll
        for (int nt = 0; nt < 4; nt++)
            #pragma unroll
            for (int r = 0; r < 4; r++) acc[mt][nt][r] = 0.f;

    // Per-lane ldmatrix address component (A): row = warp_m*64 + (lane&15),
    // koff = (lane>>4)*8
    const uint32_t a_lane_off =
        (uint32_t)(((warp_m * 64 + (lane & 15)) * PITCH + (lane >> 4) * 8) * 2);

    prefetch(0);

    for (int c = 0; c < NCHUNK; c++) {
        if (c + 1 < NCHUNK) {
            prefetch(c + 1);
            cp_wait<1>();
        } else {
            cp_wait<0>();
        }
        __syncthreads();

        const uint32_t abuf = sb + (uint32_t)(c & 1) * TILE_BYTES_S;
        const char* bbuf = smem + A_REGION + (c & 1) * TILE_BYTES_S;

        #pragma unroll
        for (int ks = 0; ks < 4; ks++) {
            const int k0 = ks * 16;
            uint32_t af[4][4];
            #pragma unroll
            for (int mt = 0; mt < 4; mt++)
                ldmatrix_x4(af[mt][0], af[mt][1], af[mt][2], af[mt][3],
                            abuf + a_lane_off + (uint32_t)((mt * 16 * PITCH + k0) * 2));
            uint32_t bf[4][2];
            #pragma unroll
            for (int nt = 0; nt < 4; nt++) {
                const int n = warp_n * 32 + nt * 8 + group;
                bf[nt][0] = *(const uint32_t*)(bbuf + (n * PITCH + k0 + 2 * tig) * 2);
                bf[nt][1] = *(const uint32_t*)(bbuf + (n * PITCH + k0 + 2 * tig + 8) * 2);
            }
            #pragma unroll
            for (int mt = 0; mt < 4; mt++)
                #pragma unroll
                for (int nt = 0; nt < 4; nt++)
                    mma_f16(acc[mt][nt], af[mt], bf[nt]);
        }
        __syncthreads();   // buffer (c&1) reused by prefetch(c+2)
    }

    // Epilogue: out = weight[tok] + acc
    #pragma unroll
    for (int mt = 0; mt < 4; mt++) {
        #pragma unroll
        for (int mo = 0; mo < 2; mo++) {
            const int row = warp_m * 64 + mt * 16 + mo * 8 + group;
            const int tok = s_tok[row];
            const float* wrow = weight + (size_t)tok * DIM + n0;
            float* orow = out + (size_t)(m0 + row) * DIM + n0;
            #pragma unroll
            for (int nt = 0; nt < 4; nt++) {
                const int col = warp_n * 32 + nt * 8 + tig * 2;
                float2 w = *(const float2*)(wrow + col);
                float2 o;
                o.x = w.x + acc[mt][nt][mo * 2 + 0];
                o.y = w.y + acc[mt][nt][mo * 2 + 1];
                *(float2*)(orow + col) = o;
            }
        }
    }
}

// ============================================================================
// Launch
// ============================================================================
extern "C" void kernel_launch(void* const* d_in, const int* in_sizes, int n_in,
                              void* d_out, int out_size) {
    const int*   x      = (const int*)d_in[0];       // [16384] int32
    const float* weight = (const float*)d_in[1];     // [128000, 1024]
    const float* A      = (const float*)d_in[2];     // [128000, 256]
    const float* B      = (const float*)d_in[3];     // [256, 1024]
    float* out          = (float*)d_out;             // [16384, 1024]

    (void)in_sizes; (void)n_in; (void)out_size;

    {
        dim3 grid(DIM / 32, RANK / 32);
        dim3 block(32, 8);
        transpose_b_kernel<<<grid, block>>>(B);
    }
    {
        gather_a_kernel<<<M_TOTAL / 8, 256>>>(x, A);
    }
    {
        static bool attr_set = false;
        if (!attr_set) {
            cudaFuncSetAttribute(lora_embed_kernel,
                                 cudaFuncAttributeMaxDynamicSharedMemorySize, SMEM_BYTES);
            attr_set = true;
        }
        dim3 grid(DIM / TILE_N, M_TOTAL / TILE_M);   // (8, 128) — N fastest
        lora_embed_kernel<<<grid, 256, SMEM_BYTES>>>(x, weight, out);
    }
}

// round 4
// speedup vs baseline: 1.8415x; 1.2521x over previous
#include <cuda_runtime.h>
#include <cuda_fp16.h>
#include <cstdint>

// ============================================================================
// y[t, :] = weight[x[t], :] + A[x[t], :] @ B
//   tokens M = 16384, DIM N = 1024, RANK K = 256
// mma.sync.m16n8k16.f32.f16.f16.f32, 2 CTAs/SM, ldmatrix for both operands.
// ============================================================================
static constexpr int M_TOTAL = 16384;
static constexpr int DIM     = 1024;
static constexpr int RANK    = 256;

static constexpr int TILE_M  = 128;
static constexpr int TILE_N  = 128;
static constexpr int KC      = 64;              // K chunk (halves)
static constexpr int NCHUNK  = RANK / KC;       // 4

// Smem: pitch 72 halves (144 B) -> conflict-free ldmatrix (banks 4i mod 32)
static constexpr int PITCH        = 72;
static constexpr int TILE_HALVES  = 128 * PITCH;          // 9216 halves
static constexpr int TILE_BYTES_S = TILE_HALVES * 2;      // 18432 B
static constexpr int A_REGION     = 2 * TILE_BYTES_S;     // 36864 B (2 bufs)
static constexpr int SMEM_BYTES   = 2 * A_REGION + 512;   // + tokens[128]

// Scratch: half B^T [DIM][RANK] (0.5 MB), gathered half A [M][RANK] (8 MB)
__device__ __half g_Bt[DIM * RANK];
__device__ __half g_Ah[M_TOTAL * RANK];

// ---------------------------------------------------------------------------
__device__ __forceinline__ uint32_t smem_to_u32(const void* p) {
    uint32_t a;
    asm("{ .reg .u64 t; cvta.to.shared.u64 t, %1; cvt.u32.u64 %0, t; }" : "=r"(a) : "l"(p));
    return a;
}
__device__ __forceinline__ void cp_async16(uint32_t dst, const void* src) {
    asm volatile("cp.async.cg.shared.global [%0], [%1], 16;" :: "r"(dst), "l"(src));
}
__device__ __forceinline__ void cp_commit() {
    asm volatile("cp.async.commit_group;" ::: "memory");
}
template <int N>
__device__ __forceinline__ void cp_wait() {
    asm volatile("cp.async.wait_group %0;" :: "n"(N) : "memory");
}
__device__ __forceinline__ void ldmatrix_x4(uint32_t& r0, uint32_t& r1,
                                            uint32_t& r2, uint32_t& r3, uint32_t addr) {
    asm volatile("ldmatrix.sync.aligned.m8n8.x4.shared.b16 {%0,%1,%2,%3}, [%4];"
                 : "=r"(r0), "=r"(r1), "=r"(r2), "=r"(r3) : "r"(addr));
}
__device__ __forceinline__ void mma_f16(float* c, const uint32_t* a, const uint32_t* b) {
    asm volatile(
        "mma.sync.aligned.m16n8k16.row.col.f32.f16.f16.f32 "
        "{%0,%1,%2,%3}, {%4,%5,%6,%7}, {%8,%9}, {%0,%1,%2,%3};\n"
        : "+f"(c[0]), "+f"(c[1]), "+f"(c[2]), "+f"(c[3])
        : "r"(a[0]), "r"(a[1]), "r"(a[2]), "r"(a[3]), "r"(b[0]), "r"(b[1]));
}

// ============================================================================
// Kernel 1: transpose+convert B [RANK, DIM] f32 -> g_Bt [DIM, RANK] half
// ============================================================================
__global__ void transpose_b_kernel(const float* __restrict__ B) {
    __shared__ float t[32][33];
    int n0 = blockIdx.x * 32;
    int k0 = blockIdx.y * 32;
    int tx = threadIdx.x, ty = threadIdx.y;
    #pragma unroll
    for (int j = 0; j < 32; j += 8)
        t[ty + j][tx] = B[(size_t)(k0 + ty + j) * DIM + n0 + tx];
    __syncthreads();
    #pragma unroll
    for (int j = 0; j < 32; j += 8)
        g_Bt[(size_t)(n0 + ty + j) * RANK + k0 + tx] = __float2half_rn(t[tx][ty + j]);
}

// ============================================================================
// Kernel 2: gather+convert A rows: g_Ah[t] = half(A[x[t]]). 8 rows per block.
// ============================================================================
__global__ __launch_bounds__(256)
void gather_a_kernel(const int* __restrict__ x, const float* __restrict__ A) {
    const int row  = blockIdx.x * 8 + (threadIdx.x >> 5);
    const int lane = threadIdx.x & 31;
    const int tok  = x[row];
    const float4* src = (const float4*)(A + (size_t)tok * RANK) + lane * 2;
    float4 v0 = src[0], v1 = src[1];
    __half2 h[4];
    h[0] = __floats2half2_rn(v0.x, v0.y);
    h[1] = __floats2half2_rn(v0.z, v0.w);
    h[2] = __floats2half2_rn(v1.x, v1.y);
    h[3] = __floats2half2_rn(v1.z, v1.w);
    *(uint4*)(g_Ah + (size_t)row * RANK + lane * 8) = *(const uint4*)h;
}

// ============================================================================
// Kernel 3: fused GEMM + weight-gather epilogue
//   grid: (8, 128) N fastest; block 256 = 8 warps; warp tile 64x32; 2 CTAs/SM
// ============================================================================
__global__ __launch_bounds__(256, 2)
void lora_embed_kernel(const int* __restrict__ x,
                       const float* __restrict__ weight,
                       float* __restrict__ out) {
    extern __shared__ __align__(16) char smem[];
    int* s_tok = (int*)(smem + 2 * A_REGION);

    const int tid    = threadIdx.x;
    const int wid    = tid >> 5;
    const int lane   = tid & 31;
    const int group  = lane >> 2;   // 0..7
    const int tig    = lane & 3;    // 0..3
    const int warp_m = wid >> 2;    // 0..1
    const int warp_n = wid & 3;     // 0..3

    const int n0 = blockIdx.x * TILE_N;
    const int m0 = blockIdx.y * TILE_M;

    if (tid < 128) s_tok[tid] = x[m0 + tid];

    const uint32_t sb = smem_to_u32(smem);

    // Loader mapping: 2 threads per row, each covers 32 halves (4x16B) / chunk
    const int lrow  = tid >> 1;
    const int lhalf = tid & 1;
    const __half* a_src = g_Ah + (size_t)(m0 + lrow) * RANK + lhalf * 32;
    const __half* b_src = g_Bt + (size_t)(n0 + lrow) * RANK + lhalf * 32;
    const uint32_t a_dst = sb + (lrow * PITCH + lhalf * 32) * 2;
    const uint32_t b_dst = a_dst + A_REGION;

    auto prefetch = [&](int c) {
        const uint32_t boff = (uint32_t)(c & 1) * TILE_BYTES_S;
        #pragma unroll
        for (int i = 0; i < 4; i++) {
            cp_async16(a_dst + boff + i * 16, a_src + c * KC + i * 8);
            cp_async16(b_dst + boff + i * 16, b_src + c * KC + i * 8);
        }
        cp_commit();
    };

    float acc[4][4][4];
    #pragma unroll
    for (int mt = 0; mt < 4; mt++)
        #pragma unroll
        for (int nt = 0; nt < 4; nt++)
            #pragma unroll
            for (int r = 0; r < 4; r++) acc[mt][nt][r] = 0.f;

    // A ldmatrix lane offset: row = warp_m*64 + (lane&15), koff = (lane>>4)*8
    const uint32_t a_lane_off =
        (uint32_t)(((warp_m * 64 + (lane & 15)) * PITCH + (lane >> 4) * 8) * 2);
    // B ldmatrix lane offset (x4 = mats [nlo klo, nlo khi, nhi klo, nhi khi]):
    //   mat = lane>>3: n_off = (mat>>1)*8 + (lane&7), k_off = (mat&1)*8
    const uint32_t b_lane_off =
        (uint32_t)(((warp_n * 32 + ((lane >> 4) << 3) + (lane & 7)) * PITCH
                    + ((lane >> 3) & 1) * 8) * 2);

    prefetch(0);

    for (int c = 0; c < NCHUNK; c++) {
        if (c + 1 < NCHUNK) {
            prefetch(c + 1);
            cp_wait<1>();
        } else {
            cp_wait<0>();
        }
        __syncthreads();

        const uint32_t abuf = sb + (uint32_t)(c & 1) * TILE_BYTES_S;
        const uint32_t bbuf = abuf + (uint32_t)A_REGION;

        #pragma unroll
        for (int ks = 0; ks < 4; ks++) {
            const uint32_t k0b = (uint32_t)(ks * 16 * 2);
            uint32_t af[4][4];
            #pragma unroll
            for (int mt = 0; mt < 4; mt++)
                ldmatrix_x4(af[mt][0], af[mt][1], af[mt][2], af[mt][3],
                            abuf + a_lane_off + (uint32_t)(mt * 16 * PITCH * 2) + k0b);
            uint32_t bf[4][2];
            #pragma unroll
            for (int q = 0; q < 2; q++)   // q covers nt {2q, 2q+1}
                ldmatrix_x4(bf[2 * q][0], bf[2 * q][1], bf[2 * q + 1][0], bf[2 * q + 1][1],
                            bbuf + b_lane_off + (uint32_t)(q * 16 * PITCH * 2) + k0b);
            #pragma unroll
            for (int mt = 0; mt < 4; mt++)
                #pragma unroll
                for (int nt = 0; nt < 4; nt++)
                    mma_f16(acc[mt][nt], af[mt], bf[nt]);
        }
        __syncthreads();   // buffer (c&1) reused by prefetch(c+2)
    }

    // Epilogue: out = weight[tok] + acc
    #pragma unroll
    for (int mt = 0; mt < 4; mt++) {
        #pragma unroll
        for (int mo = 0; mo < 2; mo++) {
            const int row = warp_m * 64 + mt * 16 + mo * 8 + group;
            const int tok = s_tok[row];
            const float* wrow = weight + (size_t)tok * DIM + n0;
            float* orow = out + (size_t)(m0 + row) * DIM + n0;
            #pragma unroll
            for (int nt = 0; nt < 4; nt++) {
                const int col = warp_n * 32 + nt * 8 + tig * 2;
                float2 w = *(const float2*)(wrow + col);
                float2 o;
                o.x = w.x + acc[mt][nt][mo * 2 + 0];
                o.y = w.y + acc[mt][nt][mo * 2 + 1];
                *(float2*)(orow + col) = o;
            }
        }
    }
}

// ============================================================================
// Launch
// ============================================================================
extern "C" void kernel_launch(void* const* d_in, const int* in_sizes, int n_in,
                              void* d_out, int out_size) {
    const int*   x      = (const int*)d_in[0];       // [16384] int32
    const float* weight = (const float*)d_in[1];     // [128000, 1024]
    const float* A      = (const float*)d_in[2];     // [128000, 256]
    const float* B      = (const float*)d_in[3];     // [256, 1024]
    float* out          = (float*)d_out;             // [16384, 1024]

    (void)in_sizes; (void)n_in; (void)out_size;

    {
        dim3 grid(DIM / 32, RANK / 32);
        dim3 block(32, 8);
        transpose_b_kernel<<<grid, block>>>(B);
    }
    {
        gather_a_kernel<<<M_TOTAL / 8, 256>>>(x, A);
    }
    {
        static bool attr_set = false;
        if (!attr_set) {
            cudaFuncSetAttribute(lora_embed_kernel,
                                 cudaFuncAttributeMaxDynamicSharedMemorySize, SMEM_BYTES);
            attr_set = true;
        }
        dim3 grid(DIM / TILE_N, M_TOTAL / TILE_M);   // (8, 128) — N fastest
        lora_embed_kernel<<<grid, 256, SMEM_BYTES>>>(x, weight, out);
    }
}